// round 1
// baseline (speedup 1.0000x reference)
#include <cuda_runtime.h>
#include <cfloat>

#define BB 8
#define NN 2048
#define KNBR 32
#define NPTS (BB*NN)

// ---------------- scratch (static device globals; no runtime alloc) ----------
__device__ float g_d2[(size_t)NPTS * NN];    // 134MB pairwise distances (reused per stage)
__device__ float g_sq[NPTS];
__device__ int   g_idx[NPTS * KNBR];
__device__ float g_x1[NPTS * 64];
__device__ float g_x2[NPTS * 128];
__device__ float g_xc[NPTS * 192];
__device__ float g_qp[(size_t)NPTS * 1024];  // [q | p] per point, max 2*512
__device__ float g_wc[192 * 1024];           // combined weights [Wb | Wa-Wb]

// ---------------- squared norms ----------------------------------------------
__global__ void sq_kernel(const float* __restrict__ X, float* __restrict__ sq, int C) {
    int i = blockIdx.x * blockDim.x + threadIdx.x;
    if (i < NPTS) {
        const float* r = X + (size_t)i * C;
        float s = 0.f;
        for (int c = 0; c < C; c++) s += r[c] * r[c];
        sq[i] = s;
    }
}

// ---------------- pairwise d2 = |xi|^2 + |xj|^2 - 2 xi.xj ---------------------
// grid (N/64, N/64, B), 256 threads, 64x64 tile, 4x4 per thread
__global__ void d2_kernel(const float* __restrict__ X, const float* __restrict__ sq,
                          float* __restrict__ d2, int C) {
    __shared__ __align__(16) float As[16][68];
    __shared__ __align__(16) float Bs[16][68];
    int b = blockIdx.z;
    int row0 = blockIdx.y * 64, col0 = blockIdx.x * 64;
    const float* Xb = X + (size_t)b * NN * C;
    int tid = threadIdx.x;
    int ty = tid >> 4, tx = tid & 15;
    float acc[4][4];
#pragma unroll
    for (int i = 0; i < 4; i++)
#pragma unroll
        for (int j = 0; j < 4; j++) acc[i][j] = 0.f;

    int li = tid >> 2;            // 0..63 row in tile
    int lk = (tid & 3) << 2;      // k base

    for (int k0 = 0; k0 < C; k0 += 16) {
#pragma unroll
        for (int u = 0; u < 4; u++) {
            int kk = lk + u;
            int k = k0 + kk;
            As[kk][li] = (k < C) ? Xb[(size_t)(row0 + li) * C + k] : 0.f;
            Bs[kk][li] = (k < C) ? Xb[(size_t)(col0 + li) * C + k] : 0.f;
        }
        __syncthreads();
#pragma unroll
        for (int kk = 0; kk < 16; kk++) {
            float4 a4 = *(const float4*)&As[kk][ty << 2];
            float4 b4 = *(const float4*)&Bs[kk][tx << 2];
            float a[4] = {a4.x, a4.y, a4.z, a4.w};
            float bb[4] = {b4.x, b4.y, b4.z, b4.w};
#pragma unroll
            for (int i = 0; i < 4; i++)
#pragma unroll
                for (int j = 0; j < 4; j++) acc[i][j] += a[i] * bb[j];
        }
        __syncthreads();
    }
#pragma unroll
    for (int i = 0; i < 4; i++) {
        int r = row0 + (ty << 2) + i;
        float sqr = sq[b * NN + r];
#pragma unroll
        for (int j = 0; j < 4; j++) {
            int c = col0 + (tx << 2) + j;
            float v = sqr + sq[b * NN + c] - 2.f * acc[i][j];
            if (r == c) v = FLT_MAX;   // exclude self (matches reference drop of col 0)
            d2[((size_t)b * NN + r) * NN + c] = v;
        }
    }
}

// ---------------- top-K selection (32 smallest per row, lowest-index ties) ----
// one block per point; incremental argmin: cached per-thread local minima,
// only the thread owning the extracted element rescans its strided slice.
__global__ void knn_kernel(const float* __restrict__ d2, int* __restrict__ idxout) {
    __shared__ float sd[NN];
    __shared__ float wv[8];
    __shared__ int   wi[8];
    __shared__ float gvs;
    __shared__ int   gis;
    int p = blockIdx.x;
    const float* row = d2 + (size_t)p * NN;
    int t = threadIdx.x;                // 256 threads

    for (int i = t; i < NN; i += 256) sd[i] = row[i];
    __syncthreads();

    // local min over strided ownership (i = t + u*256): conflict-free banks,
    // ascending index order -> strict < keeps lowest index
    float bv = FLT_MAX; int bi = 0x7fffffff;
#pragma unroll
    for (int u = 0; u < 8; u++) {
        int i = t + (u << 8);
        float v = sd[i];
        if (v < bv) { bv = v; bi = i; }
    }

    for (int s = 0; s < KNBR; s++) {
        // butterfly reduce within warp (all lanes get result)
        float rv = bv; int ri = bi;
#pragma unroll
        for (int off = 16; off; off >>= 1) {
            float ov = __shfl_xor_sync(0xffffffff, rv, off);
            int   oi = __shfl_xor_sync(0xffffffff, ri, off);
            if (ov < rv || (ov == rv && oi < ri)) { rv = ov; ri = oi; }
        }
        if ((t & 31) == 0) { wv[t >> 5] = rv; wi[t >> 5] = ri; }
        __syncthreads();
        if (t == 0) {
            float gv = wv[0]; int gi = wi[0];
#pragma unroll
            for (int w = 1; w < 8; w++)
                if (wv[w] < gv || (wv[w] == gv && wi[w] < gi)) { gv = wv[w]; gi = wi[w]; }
            gvs = gv; gis = gi;
            idxout[p * KNBR + s] = gi;
            sd[gi] = FLT_MAX;
        }
        __syncthreads();
        int gi = gis;
        // owner thread rescans its slice
        if ((gi & 255) == t) {
            bv = FLT_MAX; bi = 0x7fffffff;
#pragma unroll
            for (int u = 0; u < 8; u++) {
                int i = t + (u << 8);
                float v = sd[i];
                if (v < bv) { bv = v; bi = i; }
            }
        }
        __syncthreads();
    }
}

// ---------------- combined weight prep: wc = [Wb | Wa - Wb] -------------------
__global__ void prepw_kernel(const float* __restrict__ W, float* __restrict__ wc,
                             int C, int Cout) {
    int i = blockIdx.x * blockDim.x + threadIdx.x;
    if (i < C * Cout) {
        int c = i / Cout, d = i % Cout;
        float wa = W[c * Cout + d];
        float wb = W[(C + c) * Cout + d];
        wc[c * (2 * Cout) + d] = wb;
        wc[c * (2 * Cout) + Cout + d] = wa - wb;
    }
}

// ---------------- generic GEMM: C[M,N] = A[M,K] @ B[K,N] ----------------------
// grid (N/64, M/64), 256 threads, 64x64 tile, 4x4 per thread, M%64==0, N%64==0
__global__ void gemm_kernel(const float* __restrict__ A, const float* __restrict__ Bm,
                            float* __restrict__ Cm, int Kd, int Nd) {
    __shared__ __align__(16) float As[16][68];
    __shared__ __align__(16) float Bs[16][68];
    int row0 = blockIdx.y * 64, col0 = blockIdx.x * 64;
    int tid = threadIdx.x;
    int ty = tid >> 4, tx = tid & 15;
    float acc[4][4];
#pragma unroll
    for (int i = 0; i < 4; i++)
#pragma unroll
        for (int j = 0; j < 4; j++) acc[i][j] = 0.f;

    int ai = tid >> 2;
    int ak = (tid & 3) << 2;
    int bk = tid >> 6;        // 0..3
    int bn = tid & 63;

    for (int k0 = 0; k0 < Kd; k0 += 16) {
#pragma unroll
        for (int u = 0; u < 4; u++) {
            int k = k0 + ak + u;
            As[ak + u][ai] = (k < Kd) ? A[(size_t)(row0 + ai) * Kd + k] : 0.f;
        }
#pragma unroll
        for (int u = 0; u < 4; u++) {
            int kk = bk + (u << 2);
            int k = k0 + kk;
            Bs[kk][bn] = (k < Kd) ? Bm[(size_t)k * Nd + col0 + bn] : 0.f;
        }
        __syncthreads();
#pragma unroll
        for (int kk = 0; kk < 16; kk++) {
            float4 a4 = *(const float4*)&As[kk][ty << 2];
            float4 b4 = *(const float4*)&Bs[kk][tx << 2];
            float a[4] = {a4.x, a4.y, a4.z, a4.w};
            float bb[4] = {b4.x, b4.y, b4.z, b4.w};
#pragma unroll
            for (int i = 0; i < 4; i++)
#pragma unroll
                for (int j = 0; j < 4; j++) acc[i][j] += a[i] * bb[j];
        }
        __syncthreads();
    }
#pragma unroll
    for (int i = 0; i < 4; i++)
#pragma unroll
        for (int j = 0; j < 4; j++)
            Cm[(size_t)(row0 + (ty << 2) + i) * Nd + col0 + (tx << 2) + j] = acc[i][j];
}

// ---------------- gather-max + bias + activation ------------------------------
// out[p,d] = act( p_part[p,d] + bias[d] + max_j q[nbr_j, d] )
__global__ void gather_kernel(const float* __restrict__ qp, const int* __restrict__ idx,
                              const float* __restrict__ bias, float* __restrict__ out,
                              int Cout, int relu) {
    __shared__ int nbr[KNBR];
    int p = blockIdx.x;
    int b = p / NN;
    if (threadIdx.x < KNBR) nbr[threadIdx.x] = idx[p * KNBR + threadIdx.x];
    __syncthreads();
    int ld = 2 * Cout;
    size_t baserow = (size_t)b * NN;
    for (int d = threadIdx.x; d < Cout; d += blockDim.x) {
        float m = -FLT_MAX;
#pragma unroll 4
        for (int j = 0; j < KNBR; j++) {
            m = fmaxf(m, qp[(baserow + nbr[j]) * ld + d]);
        }
        float v = qp[(size_t)p * ld + Cout + d] + bias[d] + m;
        if (relu) v = fmaxf(v, 0.f);
        out[(size_t)p * Cout + d] = v;
    }
}

// ---------------- concat x1 | x2 ----------------------------------------------
__global__ void concat_kernel(const float* __restrict__ x1, const float* __restrict__ x2,
                              float* __restrict__ xc) {
    int i = blockIdx.x * blockDim.x + threadIdx.x;
    if (i < NPTS * 192) {
        int p = i / 192, c = i % 192;
        xc[i] = (c < 64) ? x1[p * 64 + c] : x2[p * 128 + (c - 64)];
    }
}

// ---------------- launch ------------------------------------------------------
extern "C" void kernel_launch(void* const* d_in, const int* in_sizes, int n_in,
                              void* d_out, int out_size) {
    const float* x  = (const float*)d_in[0];
    const float* W1 = (const float*)d_in[1];
    const float* b1 = (const float*)d_in[2];
    const float* W2 = (const float*)d_in[3];
    const float* b2 = (const float*)d_in[4];
    const float* W3 = (const float*)d_in[5];
    const float* b3 = (const float*)d_in[6];
    float* out = (float*)d_out;

    float *d2, *sqp, *x1, *x2, *xc, *qp, *wc;
    int* idxp;
    cudaGetSymbolAddress((void**)&d2,   g_d2);
    cudaGetSymbolAddress((void**)&sqp,  g_sq);
    cudaGetSymbolAddress((void**)&idxp, g_idx);
    cudaGetSymbolAddress((void**)&x1,   g_x1);
    cudaGetSymbolAddress((void**)&x2,   g_x2);
    cudaGetSymbolAddress((void**)&xc,   g_xc);
    cudaGetSymbolAddress((void**)&qp,   g_qp);
    cudaGetSymbolAddress((void**)&wc,   g_wc);

    dim3 d2grid(NN / 64, NN / 64, BB);

    // ---- stage 1: C=3 -> 64
    sq_kernel<<<(NPTS + 255) / 256, 256>>>(x, sqp, 3);
    d2_kernel<<<d2grid, 256>>>(x, sqp, d2, 3);
    knn_kernel<<<NPTS, 256>>>(d2, idxp);
    prepw_kernel<<<(3 * 64 + 255) / 256, 256>>>(W1, wc, 3, 64);
    gemm_kernel<<<dim3(128 / 64, NPTS / 64), 256>>>(x, wc, qp, 3, 128);
    gather_kernel<<<NPTS, 64>>>(qp, idxp, b1, x1, 64, 1);

    // ---- stage 2: C=64 -> 128
    sq_kernel<<<(NPTS + 255) / 256, 256>>>(x1, sqp, 64);
    d2_kernel<<<d2grid, 256>>>(x1, sqp, d2, 64);
    knn_kernel<<<NPTS, 256>>>(d2, idxp);
    prepw_kernel<<<(64 * 128 + 255) / 256, 256>>>(W2, wc, 64, 128);
    gemm_kernel<<<dim3(256 / 64, NPTS / 64), 256>>>(x1, wc, qp, 64, 256);
    gather_kernel<<<NPTS, 128>>>(qp, idxp, b2, x2, 128, 1);

    // ---- stage 3: knn on x2 (C=128), conv on concat(x1,x2) (C=192) -> 512
    sq_kernel<<<(NPTS + 255) / 256, 256>>>(x2, sqp, 128);
    d2_kernel<<<d2grid, 256>>>(x2, sqp, d2, 128);
    knn_kernel<<<NPTS, 256>>>(d2, idxp);
    concat_kernel<<<(NPTS * 192 + 255) / 256, 256>>>(x1, x2, xc);
    prepw_kernel<<<(192 * 512 + 255) / 256, 256>>>(W3, wc, 192, 512);
    gemm_kernel<<<dim3(1024 / 64, NPTS / 64), 256>>>(xc, wc, qp, 192, 1024);
    gather_kernel<<<NPTS, 256>>>(qp, idxp, b3, out, 512, 0);
}